// round 15
// baseline (speedup 1.0000x reference)
#include <cuda_runtime.h>
#include <cuda_bf16.h>
#include <cuda_fp16.h>
#include <cstdint>

// Problem constants
constexpr int kB  = 2;
constexpr int kS  = 2048;
constexpr int kH  = 512;
constexpr int kNH = 8;
constexpr int kDK = 64;
constexpr int kM  = kB * kS;       // 4096
constexpr float kScale = 0.125f;   // 1/sqrt(64)

constexpr int kHE = kB * kNH * kS * kDK;  // elems per head tensor (2M)

// Scratch (device globals; no allocations allowed)
__device__ __half g_qhi[kHE];               // Q fp16 single (pre-scaled)
__device__ __half g_khi[kHE];               // K fp16 single
__device__ __half g_vhi[kHE];               // V fp16 single
__device__ float  g_ctx[kM * kH];           // [B*S, H]

// ---------------------------------------------------------------------------
// MMA / async-copy helpers
// ---------------------------------------------------------------------------
__device__ __forceinline__ uint32_t smaddr(const void* p) {
    return (uint32_t)__cvta_generic_to_shared(p);
}
__device__ __forceinline__ void ldsm_x4(uint32_t* r, uint32_t a) {
    asm volatile("ldmatrix.sync.aligned.m8n8.x4.shared.b16 {%0,%1,%2,%3},[%4];"
        : "=r"(r[0]), "=r"(r[1]), "=r"(r[2]), "=r"(r[3]) : "r"(a));
}
__device__ __forceinline__ void ldsm_x4t(uint32_t* r, uint32_t a) {
    asm volatile("ldmatrix.sync.aligned.m8n8.x4.trans.shared.b16 {%0,%1,%2,%3},[%4];"
        : "=r"(r[0]), "=r"(r[1]), "=r"(r[2]), "=r"(r[3]) : "r"(a));
}
__device__ __forceinline__ void mma_fp16(float* c, const uint32_t* a,
                                         const uint32_t* b) {
    asm volatile(
        "mma.sync.aligned.m16n8k16.row.col.f32.f16.f16.f32 "
        "{%0,%1,%2,%3},{%4,%5,%6,%7},{%8,%9},{%0,%1,%2,%3};"
        : "+f"(c[0]), "+f"(c[1]), "+f"(c[2]), "+f"(c[3])
        : "r"(a[0]), "r"(a[1]), "r"(a[2]), "r"(a[3]), "r"(b[0]), "r"(b[1]));
}
__device__ __forceinline__ uint32_t pack_fp16(float x, float y) {
    __half2 h = __floats2half2_rn(x, y);
    return *reinterpret_cast<uint32_t*>(&h);
}
// fp16 hi/lo split of float4
__device__ __forceinline__ void split4h(float4 v, uint32_t& h0, uint32_t& h1,
                                        uint32_t& l0, uint32_t& l1) {
    __half2 a = __floats2half2_rn(v.x, v.y);
    __half2 b = __floats2half2_rn(v.z, v.w);
    h0 = *reinterpret_cast<uint32_t*>(&a);
    h1 = *reinterpret_cast<uint32_t*>(&b);
    l0 = pack_fp16(v.x - __half2float(__low2half(a)),
                   v.y - __half2float(__high2half(a)));
    l1 = pack_fp16(v.z - __half2float(__low2half(b)),
                   v.w - __half2float(__high2half(b)));
}
__device__ __forceinline__ void cp16(uint32_t dst, const void* src) {
    asm volatile("cp.async.cg.shared.global [%0],[%1],16;"
        :: "r"(dst), "l"(src));
}
__device__ __forceinline__ void cp_commit() {
    asm volatile("cp.async.commit_group;");
}
template <int N>
__device__ __forceinline__ void cp_wait() {
    asm volatile("cp.async.wait_group %0;" :: "n"(N));
}

// ---------------------------------------------------------------------------
// Tensor-core GEMM, R15: 64x128 CTA tile, occ 2, fp16 2-MMA.
// 8 warps = 2M x 4N, warp tile 32x32. K chunks of 32.
// mode 0: Q out fp16 single, scaled. mode 1: K. mode 2: V. mode 3: fp32 out.
// ---------------------------------------------------------------------------
constexpr int kXStr = 40;
constexpr int kWStr = 136;

__device__ __forceinline__ void gemm_core(
    const float* __restrict__ X, const float* __restrict__ W,
    const float* __restrict__ bias, float* __restrict__ Yout, int mode)
{
    __shared__ __half Xh[64 * kXStr], Xl[64 * kXStr];
    __shared__ __half Wh[32 * kWStr];

    const int tid  = threadIdx.x;
    const int lane = tid & 31, w = tid >> 5;
    const int wm = w >> 2, wn = w & 3;
    const int m0 = blockIdx.y << 6, n0 = blockIdx.x << 7;

    float acc[2][4][4];
#pragma unroll
    for (int mi = 0; mi < 2; ++mi)
#pragma unroll
        for (int jn = 0; jn < 4; ++jn)
#pragma unroll
            for (int i = 0; i < 4; ++i) acc[mi][jn][i] = 0.f;

    const int xr = tid >> 2, xc = (tid & 3) << 3;   // X: 64 rows, 8 fp32/thread
    const int wr = tid >> 3, wc = (tid & 7) << 4;   // W: 32 rows, 16 fp32/thread

    float4 xs[2], ws[4];
#pragma unroll
    for (int p = 0; p < 2; ++p)
        xs[p] = *(const float4*)&X[(size_t)(m0 + xr) * kH + xc + (p << 2)];
#pragma unroll
    for (int p = 0; p < 4; ++p)
        ws[p] = *(const float4*)&W[(size_t)wr * kH + n0 + wc + (p << 2)];

    for (int k0 = 0; k0 < kH; k0 += 32) {
        __syncthreads();
#pragma unroll
        for (int p = 0; p < 2; ++p) {
            uint32_t h0, h1, l0, l1;
            split4h(xs[p], h0, h1, l0, l1);
            const int xo = xr * kXStr + xc + (p << 2);
            *(uint32_t*)&Xh[xo] = h0; *(uint32_t*)&Xh[xo + 2] = h1;
            *(uint32_t*)&Xl[xo] = l0; *(uint32_t*)&Xl[xo + 2] = l1;
        }
#pragma unroll
        for (int p = 0; p < 4; ++p) {
            __half2 wa = __floats2half2_rn(ws[p].x, ws[p].y);
            __half2 wb = __floats2half2_rn(ws[p].z, ws[p].w);
            const int wo = wr * kWStr + wc + (p << 2);
            *(__half2*)&Wh[wo]     = wa;
            *(__half2*)&Wh[wo + 2] = wb;
        }
        __syncthreads();

        if (k0 + 32 < kH) {
#pragma unroll
            for (int p = 0; p < 2; ++p)
                xs[p] = *(const float4*)&X[(size_t)(m0 + xr) * kH + k0 + 32 + xc + (p << 2)];
#pragma unroll
            for (int p = 0; p < 4; ++p)
                ws[p] = *(const float4*)&W[(size_t)(k0 + 32 + wr) * kH + n0 + wc + (p << 2)];
        }

#pragma unroll
        for (int k16 = 0; k16 < 2; ++k16) {
            uint32_t afh[2][4], afl[2][4];
#pragma unroll
            for (int mi = 0; mi < 2; ++mi) {
                const int row = (wm << 5) + (mi << 4) + (lane & 15);
                const int col = (k16 << 4) + ((lane >> 4) << 3);
                ldsm_x4(afh[mi], smaddr(&Xh[row * kXStr + col]));
                ldsm_x4(afl[mi], smaddr(&Xl[row * kXStr + col]));
            }
#pragma unroll
            for (int jp = 0; jp < 2; ++jp) {
                const int brow = (k16 << 4) + (lane & 15);
                const int bcol = (wn << 5) + (jp << 4) + ((lane >> 4) << 3);
                uint32_t bh[4];
                ldsm_x4t(bh, smaddr(&Wh[brow * kWStr + bcol]));
#pragma unroll
                for (int mi = 0; mi < 2; ++mi) {
                    mma_fp16(acc[mi][2 * jp],     afh[mi], bh);
                    mma_fp16(acc[mi][2 * jp + 1], afh[mi], bh + 2);
                    mma_fp16(acc[mi][2 * jp],     afl[mi], bh);
                    mma_fp16(acc[mi][2 * jp + 1], afl[mi], bh + 2);
                }
            }
        }
    }

#pragma unroll
    for (int jn = 0; jn < 4; ++jn) {
        const int n = n0 + (wn << 5) + (jn << 3) + ((lane & 3) << 1);
        float2 bv = *(const float2*)&bias[n];
#pragma unroll
        for (int mi = 0; mi < 2; ++mi) {
#pragma unroll
            for (int half = 0; half < 2; ++half) {
                const int m = m0 + (wm << 5) + (mi << 4) + (lane >> 2) + (half << 3);
                float v0 = acc[mi][jn][half * 2 + 0] + bv.x;
                float v1 = acc[mi][jn][half * 2 + 1] + bv.y;
                if (mode == 0) { v0 *= kScale; v1 *= kScale; }
                if (mode < 3) {
                    const int b_ = m >> 11;
                    const int s_ = m & (kS - 1);
                    const int h_ = n >> 6;
                    const int d_ = n & (kDK - 1);
                    size_t off = (((size_t)(b_ * kNH + h_)) * kS + s_) * kDK + d_;
                    __half2 hv = __floats2half2_rn(v0, v1);
                    __half* dst = (mode == 0) ? g_qhi : (mode == 1) ? g_khi : g_vhi;
                    *(__half2*)&dst[off] = hv;
                } else {
                    *(float2*)&Yout[(size_t)m * kH + n] = make_float2(v0, v1);
                }
            }
        }
    }
}

__global__ __launch_bounds__(256, 2) void qkv_gemm(
    const float* __restrict__ q, const float* __restrict__ k,
    const float* __restrict__ v,
    const float* __restrict__ Wq, const float* __restrict__ Wk,
    const float* __restrict__ Wv,
    const float* __restrict__ bq, const float* __restrict__ bk,
    const float* __restrict__ bv)
{
    const int mode = blockIdx.z;
    const float* X = (mode == 0) ? q : (mode == 1) ? k : v;
    const float* W = (mode == 0) ? Wq : (mode == 1) ? Wk : Wv;
    const float* B = (mode == 0) ? bq : (mode == 1) ? bk : bv;
    gemm_core(X, W, B, nullptr, mode);
}

__global__ __launch_bounds__(256, 2) void out_gemm(
    const float* __restrict__ Wo, const float* __restrict__ bo,
    float* __restrict__ out)
{
    gemm_core(g_ctx, Wo, bo, out, 3);
}

// ---------------------------------------------------------------------------
// Tensor-core flash attention (R13/R14, unchanged — occ 2, half-tile pipeline)
// ---------------------------------------------------------------------------
constexpr int kQStr = 72;
constexpr int kTileE = 128 * kQStr;
constexpr int kStageE = 2 * kTileE;           // stage = Kh,Vh

__global__ __launch_bounds__(256, 2) void attn_kernel(const float* __restrict__ bias)
{
    extern __shared__ __half sm[];
    __half* Qh = sm;
    __half* KV = Qh + kTileE;

    const int bh = blockIdx.y;
    const int q0 = blockIdx.x << 7;
    const int tid = threadIdx.x;
    const int lane = tid & 31, w = tid >> 5;

    const size_t hb = (size_t)bh * kS * kDK;
    const __half* Kgh = g_khi + hb;
    const __half* Vgh = g_vhi + hb;
    const float* Bp = bias + (size_t)bh * kS * kS + (size_t)q0 * kS;

    const int r = tid >> 3, c8 = (tid & 7) << 3;

    // stage 0 <- tile 0 (Kh, Vh)
    {
        __half* Kh = KV;
        __half* Vh = Kh + kTileE;
#pragma unroll
        for (int u = 0; u < 4; ++u) {
            const int row = r + (u << 5);
            const size_t g = (size_t)row * kDK + c8;
            const int so = row * kQStr + c8;
            cp16(smaddr(&Kh[so]), &Kgh[g]);
            cp16(smaddr(&Vh[so]), &Vgh[g]);
        }
        cp_commit();
    }

    // Load Q tile (fp16 single)
    {
        const __half* Qgh = g_qhi + hb;
#pragma unroll
        for (int u = 0; u < 4; ++u) {
            const int row = r + (u << 5);
            *(uint4*)&Qh[row * kQStr + c8] =
                *(const uint4*)&Qgh[(size_t)(q0 + row) * kDK + c8];
        }
    }
    __syncthreads();

    // Q fragments (resident)
    uint32_t qf[4][4];
    {
        const int r0 = w << 4;
#pragma unroll
        for (int kc = 0; kc < 4; ++kc) {
            const int row = r0 + (lane & 15);
            const int col = (kc << 4) + ((lane >> 4) << 3);
            ldsm_x4(qf[kc], smaddr(&Qh[row * kQStr + col]));
        }
    }

    float O[8][4];
#pragma unroll
    for (int j = 0; j < 8; j++)
#pragma unroll
        for (int i = 0; i < 4; i++) O[j][i] = 0.f;
    float l0 = 0.f, l1 = 0.f;

    const int rq = lane >> 2;
    const int cq = (lane & 3) << 1;
    const int krow_off = (lane & 7) + ((lane >> 4) << 3);
    const int kcol_off = ((lane >> 3) & 1) << 3;
    const int vrow_off = lane & 15;
    const int vcol_off = (lane >> 4) << 3;

    const float* Bw = Bp + (size_t)((w << 4) + rq) * kS + cq;

    for (int t = 0; t < kS / 128; ++t) {
        const int k0 = t << 7;

        float br[8][4];
        uint32_t Ph[4][4];
        float acc[8][4];

        // bias prefetch for half 0
#pragma unroll
        for (int jp = 0; jp < 4; ++jp) {
            const float* bp = Bw + k0 + (jp << 4);
            float2 bA0 = __ldcs((const float2*)bp);
            float2 bB0 = __ldcs((const float2*)(bp + 8 * (size_t)kS));
            float2 bA1 = __ldcs((const float2*)(bp + 8));
            float2 bB1 = __ldcs((const float2*)(bp + 8 * (size_t)kS + 8));
            br[2 * jp][0] = bA0.x; br[2 * jp][1] = bA0.y;
            br[2 * jp][2] = bB0.x; br[2 * jp][3] = bB0.y;
            br[2 * jp + 1][0] = bA1.x; br[2 * jp + 1][1] = bA1.y;
            br[2 * jp + 1][2] = bB1.x; br[2 * jp + 1][3] = bB1.y;
        }

        // prefetch K/V tile t+1, wait for tile t
        if (t + 1 < kS / 128) {
            __half* s = KV + ((t + 1) & 1) * kStageE;
            __half* Kh = s;
            __half* Vh = Kh + kTileE;
            const int k0n = (t + 1) << 7;
#pragma unroll
            for (int u = 0; u < 4; ++u) {
                const int row = r + (u << 5);
                const size_t g = (size_t)(k0n + row) * kDK + c8;
                const int so = row * kQStr + c8;
                cp16(smaddr(&Kh[so]), &Kgh[g]);
                cp16(smaddr(&Vh[so]), &Vgh[g]);
            }
            cp_commit();
            cp_wait<1>();
        } else {
            cp_wait<0>();
        }
        __syncthreads();

        __half* s = KV + (t & 1) * kStageE;
        const __half* Kh = s;
        const __half* Vh = Kh + kTileE;

        // ---- QK half 0 ----
#pragma unroll
        for (int jp = 0; jp < 4; ++jp) {
            float* a0 = acc[2 * jp];
            float* a1 = acc[2 * jp + 1];
            a0[0] = a0[1] = a0[2] = a0[3] = 0.f;
            a1[0] = a1[1] = a1[2] = a1[3] = 0.f;
            const int rowb = (jp << 4) + krow_off;
#pragma unroll
            for (int kc = 0; kc < 4; ++kc) {
                uint32_t kb[4];
                ldsm_x4(kb, smaddr(&Kh[rowb * kQStr + (kc << 4) + kcol_off]));
                mma_fp16(a0, qf[kc], kb);
                mma_fp16(a1, qf[kc], kb + 2);
            }
        }

        // ---- exp half 0 -> Ph ----
#pragma unroll
        for (int j = 0; j < 8; ++j) {
            float p0 = __expf(acc[j][0] + br[j][0]);
            float p1 = __expf(acc[j][1] + br[j][1]);
            float p2 = __expf(acc[j][2] + br[j][2]);
            float p3 = __expf(acc[j][3] + br[j][3]);
            l0 += p0 + p1;
            l1 += p2 + p3;
            const int kc = j >> 1, bofs = (j & 1) << 1;
            Ph[kc][bofs]     = pack_fp16(p0, p1);
            Ph[kc][bofs + 1] = pack_fp16(p2, p3);
        }

        // ---- bias prefetch half 1 ----
#pragma unroll
        for (int jp = 0; jp < 4; ++jp) {
            const float* bp = Bw + k0 + ((jp + 4) << 4);
            float2 bA0 = __ldcs((const float2*)bp);
            float2 bB0 = __ldcs((const float2*)(bp + 8 * (size_t)kS));
            float2 bA1 = __ldcs((const float2*)(bp + 8));
            float2 bB1 = __ldcs((const float2*)(bp + 8 * (size_t)kS + 8));
            br[2 * jp][0] = bA0.x; br[2 * jp][1] = bA0.y;
            br[2 * jp][2] = bB0.x; br[2 * jp][3] = bB0.y;
            br[2 * jp + 1][0] = bA1.x; br[2 * jp + 1][1] = bA1.y;
            br[2 * jp + 1][2] = bB1.x; br[2 * jp + 1][3] = bB1.y;
        }

        // ---- QK half 1 ----
        float acc1[8][4];
#pragma unroll
        for (int jp = 0; jp < 4; ++jp) {
            float* a0 = acc1[2 * jp];
            float* a1 = acc1[2 * jp + 1];
            a0[0] = a0[1] = a0[2] = a0[3] = 0.f;
            a1[0] = a1[1] = a1[2] = a1[3] = 0.f;
            const int rowb = ((jp + 4) << 4) + krow_off;
#pragma unroll
            for (int kc = 0; kc < 4; ++kc) {
                uint32_t kb[4];
                ldsm_x4(kb, smaddr(&Kh[rowb * kQStr + (kc << 4) + kcol_off]));
                mma_fp16(a0, qf[kc], kb);
                mma_fp16(a1, qf[kc], kb + 2);
            }
        }

        // ---- PV half 0 ----
#pragma unroll
        for (int jp = 0; jp < 4; ++jp) {
            float* o0 = O[2 * jp];
            float* o1 = O[2 * jp + 1];
            const int colb = (jp << 4) + vcol_off;
#pragma unroll
            for (int kc = 0; kc < 4; ++kc) {
                const int rowv = (kc << 4) + vrow_off;
                uint32_t vb[4];
                ldsm_x4t(vb, smaddr(&Vh[rowv * kQStr + colb]));
                mma_fp16(o0, Ph[kc], vb);
                mma_fp16(o1, Ph[kc], vb + 2);
            }
        }

        // ---- exp half 1 -> Ph (reuse) ----
#pragma unroll
        for (int j = 0; j < 8; ++j) {
            float p0 = __expf(acc1[j][0] + br[j][0]);
            float p1 = __expf(acc1[j][1] + br[j][1]);
            float p2 = __expf(acc1[j][2] + br[j][2]);
            float p3 = __expf(acc1[j][3] + br[j][3]);
            l0 += p0 + p1;
            l1 += p2 + p3;
            const int kc = j >> 1, bofs = (j & 1) << 1;
            Ph[kc][bofs]     = pack_fp16(p0, p1);
            Ph[kc][bofs + 1] = pack_fp16(p2, p3);
        }

        // ---- PV half 1 ----
#pragma unroll
        for (int jp = 0; jp < 4; ++jp) {
            float* o0 = O[2 * jp];
            float* o1 = O[2 * jp + 1];
            const int colb = (jp << 4) + vcol_off;
#pragma unroll
            for (int kc = 0; kc < 4; ++kc) {
                const int rowv = ((kc + 4) << 4) + vrow_off;
                uint32_t vb[4];
                ldsm_x4t(vb, smaddr(&Vh[rowv * kQStr + colb]));
                mma_fp16(o0, Ph[kc], vb);
                mma_fp16(o1, Ph[kc], vb + 2);
            }
        }
        __syncthreads();
    }

    // epilogue
    l0 += __shfl_xor_sync(0xffffffffu, l0, 1);
    l0 += __shfl_xor_sync(0xffffffffu, l0, 2);
    l1 += __shfl_xor_sync(0xffffffffu, l1, 1);
    l1 += __shfl_xor_sync(0xffffffffu, l1, 2);
    const float inv0 = 1.f / l0, inv1 = 1.f / l1;

    const int b_ = bh >> 3, h_ = bh & 7;
    const int grow = q0 + (w << 4) + rq;
    float* cp = g_ctx + ((size_t)b_ * kS + grow) * kH + h_ * kDK + cq;
#pragma unroll
    for (int jn = 0; jn < 8; ++jn) {
        *(float2*)(cp + (jn << 3)) =
            make_float2(O[jn][0] * inv0, O[jn][1] * inv0);
        *(float2*)(cp + (jn << 3) + 8 * kH) =
            make_float2(O[jn][2] * inv1, O[jn][3] * inv1);
    }
}

// ---------------------------------------------------------------------------
extern "C" void kernel_launch(void* const* d_in, const int* in_sizes, int n_in,
                              void* d_out, int out_size)
{
    const float* q  = (const float*)d_in[0];
    const float* k  = (const float*)d_in[1];
    const float* v  = (const float*)d_in[2];
    const float* ab = (const float*)d_in[3];
    const float* Wq = (const float*)d_in[4];
    const float* bq = (const float*)d_in[5];
    const float* Wk = (const float*)d_in[6];
    const float* bk = (const float*)d_in[7];
    const float* Wv = (const float*)d_in[8];
    const float* bv = (const float*)d_in[9];
    const float* Wo = (const float*)d_in[10];
    const float* bo = (const float*)d_in[11];
    float* out = (float*)d_out;

    const int attn_smem = (kTileE + 2 * kStageE) * 2;   // 92160 bytes
    cudaFuncSetAttribute(attn_kernel,
                         cudaFuncAttributeMaxDynamicSharedMemorySize, attn_smem);

    dim3 blk(256);
    qkv_gemm<<<dim3(kH / 128, kM / 64, 3), blk>>>(q, k, v, Wq, Wk, Wv, bq, bk, bv);
    attn_kernel<<<dim3(kS / 128, kB * kNH), blk, attn_smem>>>(ab);
    out_gemm<<<dim3(kH / 128, kM / 64), blk>>>(Wo, bo, out);
}

// round 17
// speedup vs baseline: 1.2332x; 1.2332x over previous
#include <cuda_runtime.h>
#include <cuda_bf16.h>
#include <cuda_fp16.h>
#include <cstdint>

// Problem constants
constexpr int kB  = 2;
constexpr int kS  = 2048;
constexpr int kH  = 512;
constexpr int kNH = 8;
constexpr int kDK = 64;
constexpr int kM  = kB * kS;       // 4096
constexpr float kL2E    = 1.4426950408889634f;
constexpr float kScaleQ = 0.125f * kL2E;   // fold log2e into Q scale

constexpr int kHE = kB * kNH * kS * kDK;  // elems per head tensor (2M)

// Scratch (device globals; no allocations allowed)
__device__ __half g_qhi[kHE];               // Q fp16 (pre-scaled by 0.125*log2e)
__device__ __half g_khi[kHE];               // K fp16 single
__device__ __half g_vhi[kHE];               // V fp16 single
__device__ float  g_ctx[kM * kH];           // [B*S, H]

// ---------------------------------------------------------------------------
// MMA / async-copy helpers
// ---------------------------------------------------------------------------
__device__ __forceinline__ uint32_t smaddr(const void* p) {
    return (uint32_t)__cvta_generic_to_shared(p);
}
__device__ __forceinline__ void ldsm_x4(uint32_t* r, uint32_t a) {
    asm volatile("ldmatrix.sync.aligned.m8n8.x4.shared.b16 {%0,%1,%2,%3},[%4];"
        : "=r"(r[0]), "=r"(r[1]), "=r"(r[2]), "=r"(r[3]) : "r"(a));
}
__device__ __forceinline__ void ldsm_x4t(uint32_t* r, uint32_t a) {
    asm volatile("ldmatrix.sync.aligned.m8n8.x4.trans.shared.b16 {%0,%1,%2,%3},[%4];"
        : "=r"(r[0]), "=r"(r[1]), "=r"(r[2]), "=r"(r[3]) : "r"(a));
}
__device__ __forceinline__ void mma_fp16(float* c, const uint32_t* a,
                                         const uint32_t* b) {
    asm volatile(
        "mma.sync.aligned.m16n8k16.row.col.f32.f16.f16.f32 "
        "{%0,%1,%2,%3},{%4,%5,%6,%7},{%8,%9},{%0,%1,%2,%3};"
        : "+f"(c[0]), "+f"(c[1]), "+f"(c[2]), "+f"(c[3])
        : "r"(a[0]), "r"(a[1]), "r"(a[2]), "r"(a[3]), "r"(b[0]), "r"(b[1]));
}
__device__ __forceinline__ uint32_t pack_fp16(float x, float y) {
    __half2 h = __floats2half2_rn(x, y);
    return *reinterpret_cast<uint32_t*>(&h);
}
__device__ __forceinline__ float ex2f(float x) {
    float r;
    asm("ex2.approx.f32 %0, %1;" : "=f"(r) : "f"(x));
    return r;
}
// fp16 hi/lo split of float4
__device__ __forceinline__ void split4h(float4 v, uint32_t& h0, uint32_t& h1,
                                        uint32_t& l0, uint32_t& l1) {
    __half2 a = __floats2half2_rn(v.x, v.y);
    __half2 b = __floats2half2_rn(v.z, v.w);
    h0 = *reinterpret_cast<uint32_t*>(&a);
    h1 = *reinterpret_cast<uint32_t*>(&b);
    l0 = pack_fp16(v.x - __half2float(__low2half(a)),
                   v.y - __half2float(__high2half(a)));
    l1 = pack_fp16(v.z - __half2float(__low2half(b)),
                   v.w - __half2float(__high2half(b)));
}
__device__ __forceinline__ void cp16(uint32_t dst, const void* src) {
    asm volatile("cp.async.cg.shared.global [%0],[%1],16;"
        :: "r"(dst), "l"(src));
}
__device__ __forceinline__ void cp_commit() {
    asm volatile("cp.async.commit_group;");
}
template <int N>
__device__ __forceinline__ void cp_wait() {
    asm volatile("cp.async.wait_group %0;" :: "n"(N));
}

// ---------------------------------------------------------------------------
// Tensor-core GEMM, R17: 128x128 CTA, fp16 2-MMA, 2-stage smem ping-pong
// (one __syncthreads per K-chunk). Dynamic smem: 2 x 29184 B = 58368 B.
// mode 0: Q out fp16 scaled by kScaleQ. mode 1: K. mode 2: V. mode 3: fp32.
// ---------------------------------------------------------------------------
constexpr int kXStr = 40;
constexpr int kWStr = 136;
constexpr int kGXh = 128 * kXStr;                 // Xh elems per stage
constexpr int kGWh = 32 * kWStr;                  // Wh elems per stage
constexpr int kGStage = 2 * kGXh + kGWh;          // Xh, Xl, Wh (halfs)

__device__ __forceinline__ void gemm_core(
    const float* __restrict__ X, const float* __restrict__ W,
    const float* __restrict__ bias, float* __restrict__ Yout, int mode)
{
    extern __shared__ __half gsm[];

    const int tid  = threadIdx.x;
    const int lane = tid & 31, w = tid >> 5;
    const int wm = w >> 1, wn = w & 1;
    const int m0 = blockIdx.y << 7, n0 = blockIdx.x << 7;

    float acc[2][8][4];
#pragma unroll
    for (int mi = 0; mi < 2; ++mi)
#pragma unroll
        for (int jn = 0; jn < 8; ++jn)
#pragma unroll
            for (int i = 0; i < 4; ++i) acc[mi][jn][i] = 0.f;

    const int xr = tid >> 3, xc = (tid & 7) << 2;
    const int wr = tid >> 5, wc = (tid & 31) << 2;

    float4 xs[4], ws[4];
#pragma unroll
    for (int p = 0; p < 4; ++p) {
        xs[p] = *(const float4*)&X[(size_t)(m0 + xr + (p << 5)) * kH + xc];
        ws[p] = *(const float4*)&W[(size_t)(wr + (p << 3)) * kH + n0 + wc];
    }

    auto store_stage = [&](int st) {
        __half* Xh = gsm + st * kGStage;
        __half* Xl = Xh + kGXh;
        __half* Wh = Xl + kGXh;
#pragma unroll
        for (int p = 0; p < 4; ++p) {
            uint32_t h0, h1, l0, l1;
            split4h(xs[p], h0, h1, l0, l1);
            const int xo = (xr + (p << 5)) * kXStr + xc;
            *(uint32_t*)&Xh[xo] = h0; *(uint32_t*)&Xh[xo + 2] = h1;
            *(uint32_t*)&Xl[xo] = l0; *(uint32_t*)&Xl[xo + 2] = l1;
            __half2 wa = __floats2half2_rn(ws[p].x, ws[p].y);
            __half2 wb = __floats2half2_rn(ws[p].z, ws[p].w);
            const int wo = (wr + (p << 3)) * kWStr + wc;
            *(__half2*)&Wh[wo]     = wa;
            *(__half2*)&Wh[wo + 2] = wb;
        }
    };

    store_stage(0);
    __syncthreads();

    for (int t = 0; t < kH / 32; ++t) {
        // issue global loads for chunk t+1
        if (t + 1 < kH / 32) {
            const int k0n = (t + 1) << 5;
#pragma unroll
            for (int p = 0; p < 4; ++p) {
                xs[p] = *(const float4*)&X[(size_t)(m0 + xr + (p << 5)) * kH + k0n + xc];
                ws[p] = *(const float4*)&W[(size_t)(k0n + wr + (p << 3)) * kH + n0 + wc];
            }
        }

        // MMA on stage t
        const __half* Xh = gsm + (t & 1) * kGStage;
        const __half* Xl = Xh + kGXh;
        const __half* Wh = Xl + kGXh;
#pragma unroll
        for (int k16 = 0; k16 < 2; ++k16) {
            uint32_t afh[2][4], afl[2][4];
#pragma unroll
            for (int mi = 0; mi < 2; ++mi) {
                const int row = (wm << 5) + (mi << 4) + (lane & 15);
                const int col = (k16 << 4) + ((lane >> 4) << 3);
                ldsm_x4(afh[mi], smaddr(&Xh[row * kXStr + col]));
                ldsm_x4(afl[mi], smaddr(&Xl[row * kXStr + col]));
            }
#pragma unroll
            for (int jp = 0; jp < 4; ++jp) {
                const int brow = (k16 << 4) + (lane & 15);
                const int bcol = (wn << 6) + (jp << 4) + ((lane >> 4) << 3);
                uint32_t bh[4];
                ldsm_x4t(bh, smaddr(&Wh[brow * kWStr + bcol]));
#pragma unroll
                for (int mi = 0; mi < 2; ++mi) {
                    mma_fp16(acc[mi][2 * jp],     afh[mi], bh);
                    mma_fp16(acc[mi][2 * jp + 1], afh[mi], bh + 2);
                    mma_fp16(acc[mi][2 * jp],     afl[mi], bh);
                    mma_fp16(acc[mi][2 * jp + 1], afl[mi], bh + 2);
                }
            }
        }

        // convert+store chunk t+1 into the other stage; single barrier
        if (t + 1 < kH / 32) {
            store_stage((t + 1) & 1);
            __syncthreads();
        }
    }

#pragma unroll
    for (int jn = 0; jn < 8; ++jn) {
        const int n = n0 + (wn << 6) + (jn << 3) + ((lane & 3) << 1);
        float2 bv = *(const float2*)&bias[n];
#pragma unroll
        for (int mi = 0; mi < 2; ++mi) {
#pragma unroll
            for (int half = 0; half < 2; ++half) {
                const int m = m0 + (wm << 5) + (mi << 4) + (lane >> 2) + (half << 3);
                float v0 = acc[mi][jn][half * 2 + 0] + bv.x;
                float v1 = acc[mi][jn][half * 2 + 1] + bv.y;
                if (mode == 0) { v0 *= kScaleQ; v1 *= kScaleQ; }
                if (mode < 3) {
                    const int b_ = m >> 11;
                    const int s_ = m & (kS - 1);
                    const int h_ = n >> 6;
                    const int d_ = n & (kDK - 1);
                    size_t off = (((size_t)(b_ * kNH + h_)) * kS + s_) * kDK + d_;
                    __half2 hv = __floats2half2_rn(v0, v1);
                    __half* dst = (mode == 0) ? g_qhi : (mode == 1) ? g_khi : g_vhi;
                    *(__half2*)&dst[off] = hv;
                } else {
                    *(float2*)&Yout[(size_t)m * kH + n] = make_float2(v0, v1);
                }
            }
        }
    }
}

__global__ __launch_bounds__(256, 1) void qkv_gemm(
    const float* __restrict__ q, const float* __restrict__ k,
    const float* __restrict__ v,
    const float* __restrict__ Wq, const float* __restrict__ Wk,
    const float* __restrict__ Wv,
    const float* __restrict__ bq, const float* __restrict__ bk,
    const float* __restrict__ bv)
{
    const int mode = blockIdx.z;
    const float* X = (mode == 0) ? q : (mode == 1) ? k : v;
    const float* W = (mode == 0) ? Wq : (mode == 1) ? Wk : Wv;
    const float* B = (mode == 0) ? bq : (mode == 1) ? bk : bv;
    gemm_core(X, W, B, nullptr, mode);
}

__global__ __launch_bounds__(256, 1) void out_gemm(
    const float* __restrict__ Wo, const float* __restrict__ bo,
    float* __restrict__ out)
{
    gemm_core(g_ctx, Wo, bo, out, 3);
}

// ---------------------------------------------------------------------------
// Tensor-core flash attention. R17 (R13/R14 frame):
//  - exp: fp32 ex2.approx (log2e pre-folded into Q scale and bias prefetch)
//  - l via ones-MMA (consistent with quantized P used in PV)
// ---------------------------------------------------------------------------
constexpr int kQStr = 72;
constexpr int kTileE = 128 * kQStr;
constexpr int kStageE = 2 * kTileE;           // stage = Kh,Vh

__global__ __launch_bounds__(256, 2) void attn_kernel(const float* __restrict__ bias)
{
    extern __shared__ __half sm[];
    __half* Qh = sm;
    __half* KV = Qh + kTileE;

    const int bh = blockIdx.y;
    const int q0 = blockIdx.x << 7;
    const int tid = threadIdx.x;
    const int lane = tid & 31, w = tid >> 5;

    const size_t hb = (size_t)bh * kS * kDK;
    const __half* Kgh = g_khi + hb;
    const __half* Vgh = g_vhi + hb;
    const float* Bp = bias + (size_t)bh * kS * kS + (size_t)q0 * kS;

    const int r = tid >> 3, c8 = (tid & 7) << 3;

    // stage 0 <- tile 0 (Kh, Vh)
    {
        __half* Kh = KV;
        __half* Vh = Kh + kTileE;
#pragma unroll
        for (int u = 0; u < 4; ++u) {
            const int row = r + (u << 5);
            const size_t g = (size_t)row * kDK + c8;
            const int so = row * kQStr + c8;
            cp16(smaddr(&Kh[so]), &Kgh[g]);
            cp16(smaddr(&Vh[so]), &Vgh[g]);
        }
        cp_commit();
    }

    // Load Q tile (fp16, pre-scaled)
    {
        const __half* Qgh = g_qhi + hb;
#pragma unroll
        for (int u = 0; u < 4; ++u) {
            const int row = r + (u << 5);
            *(uint4*)&Qh[row * kQStr + c8] =
                *(const uint4*)&Qgh[(size_t)(q0 + row) * kDK + c8];
        }
    }
    __syncthreads();

    // Q fragments (resident)
    uint32_t qf[4][4];
    {
        const int r0 = w << 4;
#pragma unroll
        for (int kc = 0; kc < 4; ++kc) {
            const int row = r0 + (lane & 15);
            const int col = (kc << 4) + ((lane >> 4) << 3);
            ldsm_x4(qf[kc], smaddr(&Qh[row * kQStr + col]));
        }
    }

    float O[8][4];
#pragma unroll
    for (int j = 0; j < 8; j++)
#pragma unroll
        for (int i = 0; i < 4; i++) O[j][i] = 0.f;
    float lacc[4] = {0.f, 0.f, 0.f, 0.f};
    const uint32_t ones2[2] = {0x3C003C00u, 0x3C003C00u};

    const int rq = lane >> 2;
    const int cq = (lane & 3) << 1;
    const int krow_off = (lane & 7) + ((lane >> 4) << 3);
    const int kcol_off = ((lane >> 3) & 1) << 3;
    const int vrow_off = lane & 15;
    const int vcol_off = (lane >> 4) << 3;

    const float* Bw = Bp + (size_t)((w << 4) + rq) * kS + cq;

    for (int t = 0; t < kS / 128; ++t) {
        const int k0 = t << 7;

        float br[8][4];
        uint32_t Ph[4][4];
        float acc[8][4];

        // bias prefetch for half 0, pre-scaled by log2e
#pragma unroll
        for (int jp = 0; jp < 4; ++jp) {
            const float* bp = Bw + k0 + (jp << 4);
            float2 bA0 = __ldcs((const float2*)bp);
            float2 bB0 = __ldcs((const float2*)(bp + 8 * (size_t)kS));
            float2 bA1 = __ldcs((const float2*)(bp + 8));
            float2 bB1 = __ldcs((const float2*)(bp + 8 * (size_t)kS + 8));
            br[2 * jp][0] = bA0.x * kL2E; br[2 * jp][1] = bA0.y * kL2E;
            br[2 * jp][2] = bB0.x * kL2E; br[2 * jp][3] = bB0.y * kL2E;
            br[2 * jp + 1][0] = bA1.x * kL2E; br[2 * jp + 1][1] = bA1.y * kL2E;
            br[2 * jp + 1][2] = bB1.x * kL2E; br[2 * jp + 1][3] = bB1.y * kL2E;
        }

        // prefetch K/V tile t+1, wait for tile t
        if (t + 1 < kS / 128) {
            __half* s = KV + ((t + 1) & 1) * kStageE;
            __half* Kh = s;
            __half* Vh = Kh + kTileE;
            const int k0n = (t + 1) << 7;
#pragma unroll
            for (int u = 0; u < 4; ++u) {
                const int row = r + (u << 5);
                const size_t g = (size_t)(k0n + row) * kDK + c8;
                const int so = row * kQStr + c8;
                cp16(smaddr(&Kh[so]), &Kgh[g]);
                cp16(smaddr(&Vh[so]), &Vgh[g]);
            }
            cp_commit();
            cp_wait<1>();
        } else {
            cp_wait<0>();
        }
        __syncthreads();

        __half* s = KV + (t & 1) * kStageE;
        const __half* Kh = s;
        const __half* Vh = Kh + kTileE;

        // ---- QK half 0 ----
#pragma unroll
        for (int jp = 0; jp < 4; ++jp) {
            float* a0 = acc[2 * jp];
            float* a1 = acc[2 * jp + 1];
            a0[0] = a0[1] = a0[2] = a0[3] = 0.f;
            a1[0] = a1[1] = a1[2] = a1[3] = 0.f;
            const int rowb = (jp << 4) + krow_off;
#pragma unroll
            for (int kc = 0; kc < 4; ++kc) {
                uint32_t kb[4];
                ldsm_x4(kb, smaddr(&Kh[rowb * kQStr + (kc << 4) + kcol_off]));
                mma_fp16(a0, qf[kc], kb);
                mma_fp16(a1, qf[kc], kb + 2);
            }
        }

        // ---- exp half 0 -> Ph (fp32 ex2, then pack) ----
#pragma unroll
        for (int j = 0; j < 8; ++j) {
            float p0 = ex2f(acc[j][0] + br[j][0]);
            float p1 = ex2f(acc[j][1] + br[j][1]);
            float p2 = ex2f(acc[j][2] + br[j][2]);
            float p3 = ex2f(acc[j][3] + br[j][3]);
            const int kc = j >> 1, bofs = (j & 1) << 1;
            Ph[kc][bofs]     = pack_fp16(p0, p1);
            Ph[kc][bofs + 1] = pack_fp16(p2, p3);
        }
        // l += P @ ones
#pragma unroll
        for (int kc = 0; kc < 4; ++kc) mma_fp16(lacc, Ph[kc], ones2);

        // ---- bias prefetch half 1 (pre-scaled) ----
#pragma unroll
        for (int jp = 0; jp < 4; ++jp) {
            const float* bp = Bw + k0 + ((jp + 4) << 4);
            float2 bA0 = __ldcs((const float2*)bp);
            float2 bB0 = __ldcs((const float2*)(bp + 8 * (size_t)kS));
            float2 bA1 = __ldcs((const float2*)(bp + 8));
            float2 bB1 = __ldcs((const float2*)(bp + 8 * (size_t)kS + 8));
            br[2 * jp][0] = bA0.x * kL2E; br[2 * jp][1] = bA0.y * kL2E;
            br[2 * jp][2] = bB0.x * kL2E; br[2 * jp][3] = bB0.y * kL2E;
            br[2 * jp + 1][0] = bA1.x * kL2E; br[2 * jp + 1][1] = bA1.y * kL2E;
            br[2 * jp + 1][2] = bB1.x * kL2E; br[2 * jp + 1][3] = bB1.y * kL2E;
        }

        // ---- QK half 1 ----
        float acc1[8][4];
#pragma unroll
        for (int jp = 0; jp < 4; ++jp) {
            float* a0 = acc1[2 * jp];
            float* a1 = acc1[2 * jp + 1];
            a0[0] = a0[1] = a0[2] = a0[3] = 0.f;
            a1[0] = a1[1] = a1[2] = a1[3] = 0.f;
            const int rowb = ((jp + 4) << 4) + krow_off;
#pragma unroll
            for (int kc = 0; kc < 4; ++kc) {
                uint32_t kb[4];
                ldsm_x4(kb, smaddr(&Kh[rowb * kQStr + (kc << 4) + kcol_off]));
                mma_fp16(a0, qf[kc], kb);
                mma_fp16(a1, qf[kc], kb + 2);
            }
        }

        // ---- PV half 0 ----
#pragma unroll
        for (int jp = 0; jp < 4; ++jp) {
            float* o0 = O[2 * jp];
            float* o1 = O[2 * jp + 1];
            const int colb = (jp << 4) + vcol_off;
#pragma unroll
            for (int kc = 0; kc < 4; ++kc) {
                const int rowv = (kc << 4) + vrow_off;
                uint32_t vb[4];
                ldsm_x4t(vb, smaddr(&Vh[rowv * kQStr + colb]));
                mma_fp16(o0, Ph[kc], vb);
                mma_fp16(o1, Ph[kc], vb + 2);
            }
        }

        // ---- exp half 1 -> Ph (reuse) ----
#pragma unroll
        for (int j = 0; j < 8; ++j) {
            float p0 = ex2f(acc1[j][0] + br[j][0]);
            float p1 = ex2f(acc1[j][1] + br[j][1]);
            float p2 = ex2f(acc1[j][2] + br[j][2]);
            float p3 = ex2f(acc1[j][3] + br[j][3]);
            const int kc = j >> 1, bofs = (j & 1) << 1;
            Ph[kc][bofs]     = pack_fp16(p0, p1);
            Ph[kc][bofs + 1] = pack_fp16(p2, p3);
        }
#pragma unroll
        for (int kc = 0; kc < 4; ++kc) mma_fp16(lacc, Ph[kc], ones2);

        // ---- PV half 1 ----
#pragma unroll
        for (int jp = 0; jp < 4; ++jp) {
            float* o0 = O[2 * jp];
            float* o1 = O[2 * jp + 1];
            const int colb = (jp << 4) + vcol_off;
#pragma unroll
            for (int kc = 0; kc < 4; ++kc) {
                const int rowv = ((kc + 4) << 4) + vrow_off;
                uint32_t vb[4];
                ldsm_x4t(vb, smaddr(&Vh[rowv * kQStr + colb]));
                mma_fp16(o0, Ph[kc], vb);
                mma_fp16(o1, Ph[kc], vb + 2);
            }
        }
        __syncthreads();
    }

    // epilogue: l from the ones-MMA accumulator
    const float inv0 = 1.f / lacc[0], inv1 = 1.f / lacc[2];

    const int b_ = bh >> 3, h_ = bh & 7;
    const int grow = q0 + (w << 4) + rq;
    float* cp = g_ctx + ((size_t)b_ * kS + grow) * kH + h_ * kDK + cq;
#pragma unroll
    for (int jn = 0; jn < 8; ++jn) {
        *(float2*)(cp + (jn << 3)) =
            make_float2(O[jn][0] * inv0, O[jn][1] * inv0);
        *(float2*)(cp + (jn << 3) + 8 * kH) =
            make_float2(O[jn][2] * inv1, O[jn][3] * inv1);
    }
}

// ---------------------------------------------------------------------------
extern "C" void kernel_launch(void* const* d_in, const int* in_sizes, int n_in,
                              void* d_out, int out_size)
{
    const float* q  = (const float*)d_in[0];
    const float* k  = (const float*)d_in[1];
    const float* v  = (const float*)d_in[2];
    const float* ab = (const float*)d_in[3];
    const float* Wq = (const float*)d_in[4];
    const float* bq = (const float*)d_in[5];
    const float* Wk = (const float*)d_in[6];
    const float* bk = (const float*)d_in[7];
    const float* Wv = (const float*)d_in[8];
    const float* bv = (const float*)d_in[9];
    const float* Wo = (const float*)d_in[10];
    const float* bo = (const float*)d_in[11];
    float* out = (float*)d_out;

    const int attn_smem = (kTileE + 2 * kStageE) * 2;   // 92160 bytes
    const int gemm_smem = 2 * kGStage * 2;              // 58368 bytes
    cudaFuncSetAttribute(attn_kernel,
                         cudaFuncAttributeMaxDynamicSharedMemorySize, attn_smem);
    cudaFuncSetAttribute(qkv_gemm,
                         cudaFuncAttributeMaxDynamicSharedMemorySize, gemm_smem);
    cudaFuncSetAttribute(out_gemm,
                         cudaFuncAttributeMaxDynamicSharedMemorySize, gemm_smem);

    dim3 blk(256);
    qkv_gemm<<<dim3(kH / 128, kM / 128, 3), blk, gemm_smem>>>(
        q, k, v, Wq, Wk, Wv, bq, bk, bv);
    attn_kernel<<<dim3(kS / 128, kB * kNH), blk, attn_smem>>>(ab);
    out_gemm<<<dim3(kH / 128, kM / 128), blk, gemm_smem>>>(Wo, bo, out);
}